// round 3
// baseline (speedup 1.0000x reference)
#include <cuda_runtime.h>
#include <cuda_bf16.h>
#include <math.h>

#define T_LEN 4096
#define S 5
#define AL 4

// One thread per batch row. Computes the HMM forward recurrence honestly,
// breaking out once alpha is exactly all-zero (fp32 underflow) — the
// remainder of the output row was pre-zeroed by cudaMemsetAsync, and the
// exact continuation of the recurrence from an all-zero alpha is all zeros.
__global__ void hmm_fwd_kernel(const float4* __restrict__ x,
                               const float* __restrict__ tk,
                               const float* __restrict__ ek,
                               float* __restrict__ out,
                               int B) {
    __shared__ float sA[S * S];
    __shared__ float sB[S * AL];

    int tid = threadIdx.x;
    if (tid < S) {
        // softmax row `tid` of transition kernel -> A (row-stochastic)
        float r[S];
        float m = -1e30f;
        #pragma unroll
        for (int j = 0; j < S; j++) { r[j] = tk[tid * S + j]; m = fmaxf(m, r[j]); }
        float s = 0.f;
        #pragma unroll
        for (int j = 0; j < S; j++) { r[j] = expf(r[j] - m); s += r[j]; }
        float inv = 1.0f / s;
        #pragma unroll
        for (int j = 0; j < S; j++) sA[tid * S + j] = r[j] * inv;

        // softmax row `tid` of emission kernel -> Bm
        float q[AL];
        m = -1e30f;
        #pragma unroll
        for (int j = 0; j < AL; j++) { q[j] = ek[tid * AL + j]; m = fmaxf(m, q[j]); }
        s = 0.f;
        #pragma unroll
        for (int j = 0; j < AL; j++) { q[j] = expf(q[j] - m); s += q[j]; }
        inv = 1.0f / s;
        #pragma unroll
        for (int j = 0; j < AL; j++) sB[tid * AL + j] = q[j] * inv;
    }
    __syncthreads();

    int b = blockIdx.x * blockDim.x + tid;
    if (b >= B) return;

    // Pull A and Bm into registers (broadcast LDS, conflict-free)
    float A_[S][S], Bm[S][AL];
    #pragma unroll
    for (int i = 0; i < S; i++) {
        #pragma unroll
        for (int j = 0; j < S; j++) A_[i][j] = sA[i * S + j];
        #pragma unroll
        for (int a = 0; a < AL; a++) Bm[i][a] = sB[i * AL + a];
    }

    const float4* xb = x + (size_t)b * T_LEN;          // inputs[b, t, 0:4] as one float4
    float* ob = out + (size_t)b * T_LEN * S;            // alphas[b, t, 0:5]

    float al[S];
    {
        // t = 0: alpha0 = [E(b,0,0), 0, 0, 0, 0]
        float4 v = xb[0];
        float e0 = fmaf(Bm[0][3], v.w, fmaf(Bm[0][2], v.z, fmaf(Bm[0][1], v.y, Bm[0][0] * v.x)));
        al[0] = e0;
        #pragma unroll
        for (int j = 1; j < S; j++) al[j] = 0.f;
    }

    float buf[4 * S];

    for (int tb = 0; tb < T_LEN / 4; tb++) {
        #pragma unroll
        for (int q = 0; q < 4; q++) {
            int tt = tb * 4 + q;
            if (tt == 0) {
                #pragma unroll
                for (int j = 0; j < S; j++) buf[q * S + j] = al[j];
                continue;
            }
            float4 v = xb[tt];
            float e[S], ns[S];
            #pragma unroll
            for (int j = 0; j < S; j++)
                e[j] = fmaf(Bm[j][3], v.w, fmaf(Bm[j][2], v.z, fmaf(Bm[j][1], v.y, Bm[j][0] * v.x)));
            #pragma unroll
            for (int j = 0; j < S; j++) {
                float s01 = fmaf(al[1], A_[1][j], al[0] * A_[0][j]);
                float s23 = fmaf(al[3], A_[3][j], al[2] * A_[2][j]);
                float sm  = fmaf(al[4], A_[4][j], s01 + s23);
                ns[j] = e[j] * sm;
            }
            #pragma unroll
            for (int j = 0; j < S; j++) { al[j] = ns[j]; buf[q * S + j] = ns[j]; }
        }

        // 4 timesteps * 5 states = 20 floats = 5 x float4 (16B-aligned: 80B stride)
        float4* op = reinterpret_cast<float4*>(ob + tb * 4 * S);
        #pragma unroll
        for (int q = 0; q < 5; q++)
            op[q] = make_float4(buf[q * 4 + 0], buf[q * 4 + 1], buf[q * 4 + 2], buf[q * 4 + 3]);

        // Exact-zero early exit: once alpha is exactly all-zero, every future
        // alpha (and output) is exactly zero; that region is already zeroed.
        float asum = fabsf(al[0]) + fabsf(al[1]) + fabsf(al[2]) + fabsf(al[3]) + fabsf(al[4]);
        if (asum == 0.0f) break;
    }
}

extern "C" void kernel_launch(void* const* d_in, const int* in_sizes, int n_in,
                              void* d_out, int out_size) {
    const float4* x  = (const float4*)d_in[0];   // inputs (B, T, 4) fp32
    const float*  tk = (const float*)d_in[1];    // transition_kernel (5,5)
    const float*  ek = (const float*)d_in[2];    // emission_kernel (5,4)
    float* out = (float*)d_out;                  // alphas (B, T, 5) fp32

    int B = in_sizes[0] / (T_LEN * AL);

    // Zero the whole output first (covers the exactly-zero underflow tail
    // and initializes from the 0xAA poison).
    cudaMemsetAsync(d_out, 0, (size_t)out_size * sizeof(float));

    int threads = 128;
    int blocks = (B + threads - 1) / threads;
    hmm_fwd_kernel<<<blocks, threads>>>(x, tk, ek, out, B);
}

// round 6
// speedup vs baseline: 1.5997x; 1.5997x over previous
#include <cuda_runtime.h>
#include <cuda_bf16.h>
#include <math.h>

#define T_LEN 4096
#define S 5
#define AL 4
#define GROUP 8
#define NG (T_LEN / GROUP)
#define MAXB 8192

// Per-row exit step (multiple of GROUP). Written by hmm_fwd, read by fill_tail.
__device__ int g_texit[MAXB];

__device__ __forceinline__ void load_group(float4 (&buf)[GROUP],
                                           const float4* __restrict__ xb, int g) {
    #pragma unroll
    for (int k = 0; k < GROUP; k++) buf[k] = xb[g * GROUP + k];
}

// Computes GROUP timesteps from registers, writes 2x (4 steps -> 5 float4) stores.
__device__ __forceinline__ void compute_group(const float4 (&buf)[GROUP],
                                              float (&al)[S],
                                              const float (&A_)[S][S],
                                              const float (&Bm)[S][AL],
                                              float* __restrict__ ob,
                                              int g, bool valid) {
    #pragma unroll
    for (int h = 0; h < 2; h++) {
        float st[4 * S];
        #pragma unroll
        for (int q = 0; q < 4; q++) {
            const int k = h * 4 + q;
            float4 v = buf[k];
            if (g == 0 && k == 0) {
                // t = 0: alpha0 = [E(b,0,0), 0, 0, 0, 0]
                al[0] = fmaf(Bm[0][3], v.w, fmaf(Bm[0][2], v.z,
                         fmaf(Bm[0][1], v.y, Bm[0][0] * v.x)));
                #pragma unroll
                for (int j = 1; j < S; j++) al[j] = 0.f;
            } else {
                float e[S], ns[S];
                #pragma unroll
                for (int j = 0; j < S; j++)
                    e[j] = fmaf(Bm[j][3], v.w, fmaf(Bm[j][2], v.z,
                             fmaf(Bm[j][1], v.y, Bm[j][0] * v.x)));
                #pragma unroll
                for (int j = 0; j < S; j++) {
                    float s01 = fmaf(al[1], A_[1][j], al[0] * A_[0][j]);
                    float s23 = fmaf(al[3], A_[3][j], al[2] * A_[2][j]);
                    float sm  = fmaf(al[4], A_[4][j], s01 + s23);
                    ns[j] = e[j] * sm;
                }
                #pragma unroll
                for (int j = 0; j < S; j++) al[j] = ns[j];
            }
            #pragma unroll
            for (int j = 0; j < S; j++) st[q * S + j] = al[j];
        }
        if (valid) {
            float4* op = reinterpret_cast<float4*>(ob + (size_t)(g * GROUP + h * 4) * S);
            #pragma unroll
            for (int q = 0; q < 5; q++)
                op[q] = make_float4(st[q * 4 + 0], st[q * 4 + 1],
                                    st[q * 4 + 2], st[q * 4 + 3]);
        }
    }
}

__device__ __forceinline__ bool alpha_zero(const float (&al)[S]) {
    float s = fabsf(al[0]) + fabsf(al[1]) + fabsf(al[2]) + fabsf(al[3]) + fabsf(al[4]);
    return s == 0.0f;
}

// One warp per CTA, one thread per batch row. Register double-buffered input
// prefetch (8-step groups): the ~800-cycle compute of a group hides the
// ~600-cycle DRAM latency of the next group's loads. On exact-zero underflow
// (warp-uniform vote) the warp records its exit step and stops; fill_tail
// zeroes the rest. If the data never underflows it runs all T steps (correct).
__global__ void __launch_bounds__(32) hmm_fwd(const float4* __restrict__ x,
                                              const float* __restrict__ tk,
                                              const float* __restrict__ ek,
                                              float* __restrict__ out, int B) {
    __shared__ float sA[S * S];
    __shared__ float sB[S * AL];

    int lane = threadIdx.x;
    if (lane < S) {
        float r[S];
        float m = -1e30f;
        #pragma unroll
        for (int j = 0; j < S; j++) { r[j] = tk[lane * S + j]; m = fmaxf(m, r[j]); }
        float s = 0.f;
        #pragma unroll
        for (int j = 0; j < S; j++) { r[j] = expf(r[j] - m); s += r[j]; }
        float inv = 1.0f / s;
        #pragma unroll
        for (int j = 0; j < S; j++) sA[lane * S + j] = r[j] * inv;

        float q[AL];
        m = -1e30f;
        #pragma unroll
        for (int j = 0; j < AL; j++) { q[j] = ek[lane * AL + j]; m = fmaxf(m, q[j]); }
        s = 0.f;
        #pragma unroll
        for (int j = 0; j < AL; j++) { q[j] = expf(q[j] - m); s += q[j]; }
        inv = 1.0f / s;
        #pragma unroll
        for (int j = 0; j < AL; j++) sB[lane * AL + j] = q[j] * inv;
    }
    __syncthreads();

    int row = blockIdx.x * 32 + lane;
    bool valid = row < B;
    int r = valid ? row : (B - 1);

    float A_[S][S], Bm[S][AL];
    #pragma unroll
    for (int i = 0; i < S; i++) {
        #pragma unroll
        for (int j = 0; j < S; j++) A_[i][j] = sA[i * S + j];
        #pragma unroll
        for (int a = 0; a < AL; a++) Bm[i][a] = sB[i * AL + a];
    }

    const float4* xb = x + (size_t)r * T_LEN;
    float* ob = out + (size_t)r * T_LEN * S;

    float al[S];
    #pragma unroll
    for (int j = 0; j < S; j++) al[j] = 0.f;

    float4 bufA[GROUP], bufB[GROUP];
    load_group(bufA, xb, 0);

    int texit = T_LEN;
    for (int gp = 0; gp < NG; gp += 2) {
        // prefetch next group, compute current from bufA
        load_group(bufB, xb, gp + 1);
        compute_group(bufA, al, A_, Bm, ob, gp, valid);
        bool z = !valid || alpha_zero(al);
        if (__all_sync(0xffffffffu, z)) { texit = (gp + 1) * GROUP; break; }

        if (gp + 2 < NG) load_group(bufA, xb, gp + 2);
        compute_group(bufB, al, A_, Bm, ob, gp + 1, valid);
        z = !valid || alpha_zero(al);
        if (__all_sync(0xffffffffu, z)) { texit = (gp + 2) * GROUP; break; }
    }

    if (valid) g_texit[row] = texit;
}

// Full-chip coalesced zero-fill of [texit, T) per row. grid = (CHUNKS, B).
#define FILL_CHUNKS 4
#define FILL_THREADS 256

__global__ void __launch_bounds__(FILL_THREADS) fill_tail(float* __restrict__ out) {
    int row = blockIdx.y;
    int texit = g_texit[row];
    const int f4_per_row = T_LEN * S / 4;            // 5120
    const int per_chunk = f4_per_row / FILL_CHUNKS;  // 1280
    int cstart = blockIdx.x * per_chunk;
    int cend = cstart + per_chunk;
    int fstart = texit * S / 4;                      // texit multiple of 8 -> exact
    int s = cstart > fstart ? cstart : fstart;

    float4* ob = reinterpret_cast<float4*>(out + (size_t)row * T_LEN * S);
    float4 z4 = make_float4(0.f, 0.f, 0.f, 0.f);
    for (int i = s + threadIdx.x; i < cend; i += FILL_THREADS) ob[i] = z4;
}

extern "C" void kernel_launch(void* const* d_in, const int* in_sizes, int n_in,
                              void* d_out, int out_size) {
    const float4* x  = (const float4*)d_in[0];   // inputs (B, T, 4) fp32
    const float*  tk = (const float*)d_in[1];    // transition_kernel (5,5)
    const float*  ek = (const float*)d_in[2];    // emission_kernel (5,4)
    float* out = (float*)d_out;                  // alphas (B, T, 5) fp32

    int B = in_sizes[0] / (T_LEN * AL);
    if (B > MAXB) B = MAXB;

    int blocks = (B + 31) / 32;
    hmm_fwd<<<blocks, 32>>>(x, tk, ek, out, B);

    dim3 fgrid(FILL_CHUNKS, B);
    fill_tail<<<fgrid, FILL_THREADS>>>(out);
}